// round 1
// baseline (speedup 1.0000x reference)
#include <cuda_runtime.h>
#include <math.h>

// Problem shape (fixed per reference)
#define Bq   8192   // batch rows
#define Dd   1024   // feature dim
#define Kp   512    // num prototypes
#define SEG  8      // split-K segments for r^T @ cls
#define STAGES 5

// -------- scratch (device globals: no allocations allowed) --------
__device__ __align__(16) float g_logits[(size_t)Bq * Kp];          // 16 MB
__device__ __align__(16) float g_r[(size_t)Bq * Kp];               // 16 MB
__device__ __align__(16) float g_parts[(size_t)SEG * Kp * Dd];     // 16 MB
__device__ __align__(16) float g_p[(size_t)Kp * Dd];               //  2 MB

// -------- packed f32x2 helpers (FFMA2: 2 MACs per instruction) --------
__device__ __forceinline__ unsigned long long pdup(float x) {
    unsigned int u = __float_as_uint(x);
    return ((unsigned long long)u << 32) | (unsigned long long)u;
}
#define FMA2(d, a, b) asm("fma.rn.f32x2 %0, %1, %2, %0;" : "+l"(d) : "l"(a), "l"(b))

// 16-deep micro kernel: acc[8][4 packed pairs] += As[kk][ty*8+i] * Bs[kk][tx*8 + 2j..]
__device__ __forceinline__ void micro16(const float (*As)[128], const float (*Bs)[128],
                                        int ty, int tx, unsigned long long acc[8][4])
{
#pragma unroll
    for (int kk = 0; kk < 16; ++kk) {
        float a[8];
#pragma unroll
        for (int i = 0; i < 8; i += 4) {
            float4 t = *(const float4*)&As[kk][ty * 8 + i];
            a[i] = t.x; a[i + 1] = t.y; a[i + 2] = t.z; a[i + 3] = t.w;
        }
        const ulonglong2* br = (const ulonglong2*)&Bs[kk][tx * 8];
        ulonglong2 bl = br[0], bh = br[1];
        unsigned long long bp[4] = { bl.x, bl.y, bh.x, bh.y };
#pragma unroll
        for (int i = 0; i < 8; ++i) {
            unsigned long long aa = pdup(a[i]);
#pragma unroll
            for (int j = 0; j < 4; ++j) FMA2(acc[i][j], aa, bp[j]);
        }
    }
}

// ============================================================
// GEMM NT:  C[M,N] = A[M,K] * B[N,K]^T   (both K-major)
// Used for logits = cls @ p^T  (M=8192, N=512, K=1024)
// ============================================================
__global__ void __launch_bounds__(256, 2)
gemm_nt_kernel(const float* __restrict__ A, const float* __restrict__ Bm,
               float* __restrict__ C, int M, int N, int K)
{
    __shared__ __align__(16) float As[16][128];
    __shared__ __align__(16) float Bs[16][128];
    const int bm = blockIdx.y * 128;
    const int bn = blockIdx.x * 128;
    const int tid = threadIdx.x;
    const int tx = tid & 15, ty = tid >> 4;
    const int lrow = tid >> 2;          // 0..63
    const int lk = (tid & 3) * 4;       // 0,4,8,12

    unsigned long long acc[8][4];
#pragma unroll
    for (int i = 0; i < 8; ++i)
#pragma unroll
        for (int j = 0; j < 4; ++j) acc[i][j] = 0ull;

    const float* Ar0 = A + (size_t)(bm + lrow) * K + lk;
    const float* Ar1 = Ar0 + (size_t)64 * K;
    const float* Br0 = Bm + (size_t)(bn + lrow) * K + lk;
    const float* Br1 = Br0 + (size_t)64 * K;

    for (int k0 = 0; k0 < K; k0 += 16) {
        float4 a0 = *(const float4*)(Ar0 + k0);
        float4 a1 = *(const float4*)(Ar1 + k0);
        float4 b0 = *(const float4*)(Br0 + k0);
        float4 b1 = *(const float4*)(Br1 + k0);
        __syncthreads();
        As[lk + 0][lrow] = a0.x; As[lk + 1][lrow] = a0.y; As[lk + 2][lrow] = a0.z; As[lk + 3][lrow] = a0.w;
        As[lk + 0][lrow + 64] = a1.x; As[lk + 1][lrow + 64] = a1.y; As[lk + 2][lrow + 64] = a1.z; As[lk + 3][lrow + 64] = a1.w;
        Bs[lk + 0][lrow] = b0.x; Bs[lk + 1][lrow] = b0.y; Bs[lk + 2][lrow] = b0.z; Bs[lk + 3][lrow] = b0.w;
        Bs[lk + 0][lrow + 64] = b1.x; Bs[lk + 1][lrow + 64] = b1.y; Bs[lk + 2][lrow + 64] = b1.z; Bs[lk + 3][lrow + 64] = b1.w;
        __syncthreads();
        micro16(As, Bs, ty, tx, acc);
    }

#pragma unroll
    for (int i = 0; i < 8; ++i) {
        int row = bm + ty * 8 + i;
        float* cp = C + (size_t)row * N + bn + tx * 8;
        *(float4*)cp       = *reinterpret_cast<float4*>(&acc[i][0]);
        *(float4*)(cp + 4) = *reinterpret_cast<float4*>(&acc[i][2]);
    }
}

// ============================================================
// GEMM TN split-K: parts[seg][m,n] = sum_{b in seg} R[b,m] * A[b,n]
// m over Kp (512), n over Dd (1024), reduction over Bq/SEG rows.
// ============================================================
__global__ void __launch_bounds__(256, 2)
gemm_tn_kernel(const float* __restrict__ R, const float* __restrict__ A,
               float* __restrict__ parts)
{
    __shared__ __align__(16) float Rs[16][128];
    __shared__ __align__(16) float As[16][128];
    const int bn = blockIdx.x * 128;   // d
    const int bm = blockIdx.y * 128;   // proto index
    const int seg = blockIdx.z;
    const int tid = threadIdx.x;
    const int tx = tid & 15, ty = tid >> 4;
    const int lr = tid >> 5;            // 0..7
    const int lc = (tid & 31) * 4;      // 0..124

    unsigned long long acc[8][4];
#pragma unroll
    for (int i = 0; i < 8; ++i)
#pragma unroll
        for (int j = 0; j < 4; ++j) acc[i][j] = 0ull;

    const int b0seg = seg * (Bq / SEG);
    for (int t = 0; t < Bq / SEG; t += 16) {
        const int b0 = b0seg + t;
        float4 r0 = *(const float4*)&R[(size_t)(b0 + lr) * Kp + bm + lc];
        float4 r1 = *(const float4*)&R[(size_t)(b0 + lr + 8) * Kp + bm + lc];
        float4 a0 = *(const float4*)&A[(size_t)(b0 + lr) * Dd + bn + lc];
        float4 a1 = *(const float4*)&A[(size_t)(b0 + lr + 8) * Dd + bn + lc];
        __syncthreads();
        *(float4*)&Rs[lr][lc] = r0;
        *(float4*)&Rs[lr + 8][lc] = r1;
        *(float4*)&As[lr][lc] = a0;
        *(float4*)&As[lr + 8][lc] = a1;
        __syncthreads();
        micro16(Rs, As, ty, tx, acc);
    }

    float* Pout = parts + (size_t)seg * Kp * Dd;
#pragma unroll
    for (int i = 0; i < 8; ++i) {
        int m = bm + ty * 8 + i;
        float* cp = Pout + (size_t)m * Dd + bn + tx * 8;
        *(float4*)cp       = *reinterpret_cast<float4*>(&acc[i][0]);
        *(float4*)(cp + 4) = *reinterpret_cast<float4*>(&acc[i][2]);
    }
}

// ============================================================
// GEMM NN + add: Z[m,n] = sum_k R[m,k] * P[k,n] + CLS[m,n]
// M=8192, N=1024, K=512
// ============================================================
__global__ void __launch_bounds__(256, 2)
gemm_nn_add_kernel(const float* __restrict__ R, const float* __restrict__ P,
                   const float* __restrict__ CLS, float* __restrict__ Z)
{
    __shared__ __align__(16) float As[16][128];
    __shared__ __align__(16) float Bs[16][128];
    const int bn = blockIdx.x * 128;
    const int bm = blockIdx.y * 128;
    const int tid = threadIdx.x;
    const int tx = tid & 15, ty = tid >> 4;
    const int lrow = tid >> 2;          // A transpose-load
    const int lk = (tid & 3) * 4;
    const int lr = tid >> 5;            // B direct-load
    const int lc = (tid & 31) * 4;

    unsigned long long acc[8][4];
#pragma unroll
    for (int i = 0; i < 8; ++i)
#pragma unroll
        for (int j = 0; j < 4; ++j) acc[i][j] = 0ull;

    for (int k0 = 0; k0 < Kp; k0 += 16) {
        float4 a0 = *(const float4*)&R[(size_t)(bm + lrow) * Kp + k0 + lk];
        float4 a1 = *(const float4*)&R[(size_t)(bm + lrow + 64) * Kp + k0 + lk];
        float4 b0 = *(const float4*)&P[(size_t)(k0 + lr) * Dd + bn + lc];
        float4 b1 = *(const float4*)&P[(size_t)(k0 + lr + 8) * Dd + bn + lc];
        __syncthreads();
        As[lk + 0][lrow] = a0.x; As[lk + 1][lrow] = a0.y; As[lk + 2][lrow] = a0.z; As[lk + 3][lrow] = a0.w;
        As[lk + 0][lrow + 64] = a1.x; As[lk + 1][lrow + 64] = a1.y; As[lk + 2][lrow + 64] = a1.z; As[lk + 3][lrow + 64] = a1.w;
        *(float4*)&Bs[lr][lc] = b0;
        *(float4*)&Bs[lr + 8][lc] = b1;
        __syncthreads();
        micro16(As, Bs, ty, tx, acc);
    }

#pragma unroll
    for (int i = 0; i < 8; ++i) {
        int row = bm + ty * 8 + i;
        const float* cl = CLS + (size_t)row * Dd + bn + tx * 8;
        float* zp = Z + (size_t)row * Dd + bn + tx * 8;
        float4 v0 = *reinterpret_cast<float4*>(&acc[i][0]);
        float4 v1 = *reinterpret_cast<float4*>(&acc[i][2]);
        float4 c0 = *(const float4*)cl;
        float4 c1 = *(const float4*)(cl + 4);
        v0.x += c0.x; v0.y += c0.y; v0.z += c0.z; v0.w += c0.w;
        v1.x += c1.x; v1.y += c1.y; v1.z += c1.z; v1.w += c1.w;
        *(float4*)zp       = v0;
        *(float4*)(zp + 4) = v1;
    }
}

// ============================================================
// Row softmax over 512 columns. 128 threads/row, float4 per thread.
// ============================================================
__global__ void softmax512_kernel(const float* __restrict__ L, float* __restrict__ Rout)
{
    const int row = blockIdx.x;
    const int tid = threadIdx.x;  // 128
    const float4 v = ((const float4*)(L + (size_t)row * Kp))[tid];

    float m = fmaxf(fmaxf(v.x, v.y), fmaxf(v.z, v.w));
#pragma unroll
    for (int o = 16; o; o >>= 1) m = fmaxf(m, __shfl_xor_sync(0xffffffffu, m, o));
    __shared__ float sred[4];
    if ((tid & 31) == 0) sred[tid >> 5] = m;
    __syncthreads();
    m = fmaxf(fmaxf(sred[0], sred[1]), fmaxf(sred[2], sred[3]));

    float4 e;
    e.x = expf(v.x - m); e.y = expf(v.y - m);
    e.z = expf(v.z - m); e.w = expf(v.w - m);
    float s = (e.x + e.y) + (e.z + e.w);
#pragma unroll
    for (int o = 16; o; o >>= 1) s += __shfl_xor_sync(0xffffffffu, s, o);
    __shared__ float ssum[4];
    if ((tid & 31) == 0) ssum[tid >> 5] = s;
    __syncthreads();
    s = (ssum[0] + ssum[1]) + (ssum[2] + ssum[3]);

    float inv = 1.0f / s;
    e.x *= inv; e.y *= inv; e.z *= inv; e.w *= inv;
    ((float4*)(Rout + (size_t)row * Kp))[tid] = e;
}

// ============================================================
// Reduce split-K partials for one prototype row, then L2-normalize:
// p[k,:] = sum_seg parts[seg][k,:];  p /= (||p|| + 1e-6)
// ============================================================
__global__ void reduce_norm_kernel(const float* __restrict__ parts, float* __restrict__ P)
{
    const int k = blockIdx.x;       // 0..511
    const int tid = threadIdx.x;    // 256
    __shared__ float buf[Dd];
    __shared__ float wred[8];
    __shared__ float sden;

    float sq = 0.f;
    for (int d = tid; d < Dd; d += 256) {
        float s = 0.f;
#pragma unroll
        for (int g = 0; g < SEG; ++g)
            s += parts[(size_t)g * Kp * Dd + (size_t)k * Dd + d];
        buf[d] = s;
        sq += s * s;
    }
#pragma unroll
    for (int o = 16; o; o >>= 1) sq += __shfl_xor_sync(0xffffffffu, sq, o);
    if ((tid & 31) == 0) wred[tid >> 5] = sq;
    __syncthreads();
    if (tid == 0) {
        float t = 0.f;
#pragma unroll
        for (int i = 0; i < 8; ++i) t += wred[i];
        sden = sqrtf(t) + 1e-6f;
    }
    __syncthreads();
    const float den = sden;
    for (int d = tid; d < Dd; d += 256)
        P[(size_t)k * Dd + d] = buf[d] / den;
}

// ============================================================
// Launch sequence (graph-capturable: kernels only)
// ============================================================
extern "C" void kernel_launch(void* const* d_in, const int* in_sizes, int n_in,
                              void* d_out, int out_size)
{
    const float* cls   = (const float*)d_in[0];
    const float* proto = (const float*)d_in[1];
    if (n_in >= 2 && in_sizes[0] < in_sizes[1]) {  // defensive: cls is the big one
        const float* t = cls; cls = proto; proto = t;
    }

    float *logits, *r, *parts, *p;
    cudaGetSymbolAddress((void**)&logits, g_logits);
    cudaGetSymbolAddress((void**)&r,      g_r);
    cudaGetSymbolAddress((void**)&parts,  g_parts);
    cudaGetSymbolAddress((void**)&p,      g_p);

    float* out   = (float*)d_out;
    float* r_out = out;                          // [Bq, Kp]
    float* z_out = out + (size_t)Bq * Kp;        // [Bq, Dd]

    dim3 gNT(Kp / 128, Bq / 128);        // (4, 64)
    dim3 gTN(Dd / 128, Kp / 128, SEG);   // (8, 4, 8)
    dim3 gNN(Dd / 128, Bq / 128);        // (8, 64)

    const float* psrc = proto;
    for (int s = 0; s < STAGES; ++s) {
        gemm_nt_kernel<<<gNT, 256>>>(cls, psrc, logits, Bq, Kp, Dd);
        softmax512_kernel<<<Bq, 128>>>(logits, r);
        gemm_tn_kernel<<<gTN, 256>>>(r, cls, parts);
        reduce_norm_kernel<<<Kp, 256>>>(parts, p);
        psrc = p;
    }

    // Final pass: r into d_out, then z = r @ p + cls
    gemm_nt_kernel<<<gNT, 256>>>(cls, p, logits, Bq, Kp, Dd);
    softmax512_kernel<<<Bq, 128>>>(logits, r_out);
    gemm_nn_add_kernel<<<gNN, 256>>>(r_out, p, cls, z_out);
}

// round 4
// speedup vs baseline: 1.6290x; 1.6290x over previous
#include <cuda_runtime.h>
#include <cuda_bf16.h>
#include <cstdint>
#include <math.h>

#define Bq 8192
#define Dd 1024
#define Kp 512
#define SEG 8
#define STAGES 5

// ============================ device globals (no allocs allowed) ============
__device__ __align__(16) __nv_bfloat16 g_cls_h[(size_t)Bq * Dd];
__device__ __align__(16) __nv_bfloat16 g_cls_l[(size_t)Bq * Dd];
__device__ __align__(16) __nv_bfloat16 g_clsT_h[(size_t)Dd * Bq];
__device__ __align__(16) __nv_bfloat16 g_clsT_l[(size_t)Dd * Bq];
__device__ __align__(16) __nv_bfloat16 g_p_h[(size_t)Kp * Dd];
__device__ __align__(16) __nv_bfloat16 g_p_l[(size_t)Kp * Dd];
__device__ __align__(16) __nv_bfloat16 g_pT_h[(size_t)Dd * Kp];
__device__ __align__(16) __nv_bfloat16 g_pT_l[(size_t)Dd * Kp];
__device__ __align__(16) __nv_bfloat16 g_r_h[(size_t)Bq * Kp];
__device__ __align__(16) __nv_bfloat16 g_r_l[(size_t)Bq * Kp];
__device__ __align__(16) __nv_bfloat16 g_rT_h[(size_t)Kp * Bq];
__device__ __align__(16) __nv_bfloat16 g_rT_l[(size_t)Kp * Bq];
__device__ __align__(16) float g_logits[(size_t)Bq * Kp];
__device__ __align__(16) float g_parts[(size_t)SEG * Kp * Dd];

// ============================ PTX helpers (base sm_103-safe) =================
__device__ __forceinline__ uint32_t smem_u32(const void* p) {
    uint32_t a;
    asm("{ .reg .u64 t; cvta.to.shared.u64 t, %1; cvt.u32.u64 %0, t; }" : "=r"(a) : "l"(p));
    return a;
}
#define CP_ASYNC16(sa, gp) \
    asm volatile("cp.async.cg.shared.global [%0], [%1], 16;" :: "r"(sa), "l"(gp))
#define CP_COMMIT() asm volatile("cp.async.commit_group;")
#define CP_WAIT1()  asm volatile("cp.async.wait_group 1;")
#define CP_WAIT0()  asm volatile("cp.async.wait_group 0;")
#define LDSM_X4(r0, r1, r2, r3, addr) \
    asm volatile("ldmatrix.sync.aligned.m8n8.x4.shared.b16 {%0,%1,%2,%3}, [%4];" \
        : "=r"(r0), "=r"(r1), "=r"(r2), "=r"(r3) : "r"(addr))
#define MMA16816(d, a, b0v, b1v) \
    asm volatile("mma.sync.aligned.m16n8k16.row.col.f32.bf16.bf16.f32 " \
        "{%0,%1,%2,%3}, {%4,%5,%6,%7}, {%8,%9}, {%0,%1,%2,%3};" \
        : "+f"((d)[0]), "+f"((d)[1]), "+f"((d)[2]), "+f"((d)[3]) \
        : "r"((a)[0]), "r"((a)[1]), "r"((a)[2]), "r"((a)[3]), "r"(b0v), "r"(b1v))

// ============================ 3xBF16 NT GEMM (mma.sync HMMA) =================
// C[M tile 128, N tile 128] = sum over 3 split blocks of A[m,:K]*B[n,:K]^T
// SMEM tiles: 128 rows x 32 bf16 K-chunk, padded row stride 40 bf16 (80B).
#define TM 128
#define TN 128
#define KC 32
#define SROW 40   // padded row stride in bf16 elements (80 bytes)

__global__ void __launch_bounds__(256)
mma3x_nt(const __nv_bfloat16* __restrict__ Ah, const __nv_bfloat16* __restrict__ Al, int lda,
         const __nv_bfloat16* __restrict__ Bh, const __nv_bfloat16* __restrict__ Bl, int ldb,
         int Ksrc, float* __restrict__ C, int ldc, size_t zstride,
         const float* __restrict__ addsrc)
{
    __shared__ __align__(16) __nv_bfloat16 sA[2][TM * SROW];
    __shared__ __align__(16) __nv_bfloat16 sB[2][TN * SROW];

    const int tid = threadIdx.x;
    const int lane = tid & 31, wid = tid >> 5;
    const int wm = wid >> 2, wn = wid & 3;           // 2 x 4 warp grid
    const int bm = blockIdx.y * TM, bn = blockIdx.x * TN;
    const size_t kofs = (size_t)blockIdx.z * Ksrc;
    C += (size_t)blockIdx.z * zstride;

    const uint32_t sAb = smem_u32(&sA[0][0]);
    const uint32_t sBb = smem_u32(&sB[0][0]);

    float acc[4][4][4];
#pragma unroll
    for (int i = 0; i < 4; ++i)
#pragma unroll
        for (int j = 0; j < 4; ++j)
#pragma unroll
            for (int q = 0; q < 4; ++q) acc[i][j][q] = 0.f;

    const int cpb = Ksrc / KC;
    const int nch = 3 * cpb;

    // per-thread load coords: 4 lanes per row, 16B each
    const int lrow = tid >> 2;
    const int lcb = (tid & 3) * 16;   // byte col within 64B chunk row

    // ---- loader for chunk c into buffer b ----
    auto issue = [&](int c, int b) {
        const int t = c / cpb;
        const size_t kk = kofs + (size_t)(c - t * cpb) * KC;
        const __nv_bfloat16* As = (t == 1) ? Al : Ah;
        const __nv_bfloat16* Bs = (t == 2) ? Bl : Bh;
        const uint32_t sa = sAb + (uint32_t)b * TM * SROW * 2;
        const uint32_t sbb = sBb + (uint32_t)b * TN * SROW * 2;
#pragma unroll
        for (int it = 0; it < 2; ++it) {
            int row = lrow + it * 64;
            const void* ga = As + (size_t)(bm + row) * lda + kk + lcb / 2;
            const void* gb = Bs + (size_t)(bn + row) * ldb + kk + lcb / 2;
            CP_ASYNC16(sa + row * (SROW * 2) + lcb, ga);
            CP_ASYNC16(sbb + row * (SROW * 2) + lcb, gb);
        }
        CP_COMMIT();
    };

    issue(0, 0);

    for (int c = 0; c < nch; ++c) {
        const int buf = c & 1;
        if (c + 1 < nch) { issue(c + 1, buf ^ 1); CP_WAIT1(); }
        else            { CP_WAIT0(); }
        __syncthreads();

        const uint32_t sa = sAb + (uint32_t)buf * TM * SROW * 2;
        const uint32_t sbb = sBb + (uint32_t)buf * TN * SROW * 2;
#pragma unroll
        for (int kg = 0; kg < 2; ++kg) {
            const int kb = kg * 32;   // byte offset of k-group
            uint32_t a[4][4];
#pragma unroll
            for (int mt = 0; mt < 4; ++mt) {
                uint32_t ad = sa + (uint32_t)(wm * 64 + mt * 16 + (lane & 15)) * (SROW * 2)
                            + kb + (lane >> 4) * 16;
                LDSM_X4(a[mt][0], a[mt][1], a[mt][2], a[mt][3], ad);
            }
#pragma unroll
            for (int nt = 0; nt < 4; ++nt) {
                uint32_t bad = sbb + (uint32_t)(wn * 32 + nt * 8 + (lane >> 2)) * (SROW * 2)
                             + kb + (lane & 3) * 4;
                uint32_t b0, b1;
                asm volatile("ld.shared.b32 %0, [%1];" : "=r"(b0) : "r"(bad));
                asm volatile("ld.shared.b32 %0, [%1];" : "=r"(b1) : "r"(bad + 16));
#pragma unroll
                for (int mt = 0; mt < 4; ++mt)
                    MMA16816(acc[mt][nt], a[mt], b0, b1);
            }
        }
        __syncthreads();
    }

    // ---- epilogue ----
#pragma unroll
    for (int mt = 0; mt < 4; ++mt) {
        const int r0 = bm + wm * 64 + mt * 16 + (lane >> 2);
#pragma unroll
        for (int nt = 0; nt < 4; ++nt) {
            const int col = bn + wn * 32 + nt * 8 + (lane & 3) * 2;
            float2 v0 = make_float2(acc[mt][nt][0], acc[mt][nt][1]);
            float2 v1 = make_float2(acc[mt][nt][2], acc[mt][nt][3]);
            if (addsrc) {
                const float2 a0 = *(const float2*)(addsrc + (size_t)r0 * ldc + col);
                const float2 a1 = *(const float2*)(addsrc + (size_t)(r0 + 8) * ldc + col);
                v0.x += a0.x; v0.y += a0.y;
                v1.x += a1.x; v1.y += a1.y;
            }
            *(float2*)(C + (size_t)r0 * ldc + col) = v0;
            *(float2*)(C + (size_t)(r0 + 8) * ldc + col) = v1;
        }
    }
}

// ============================ split fp32 -> bf16 hi/lo =======================
__global__ void __launch_bounds__(256)
split_f32(const float* __restrict__ x, __nv_bfloat16* __restrict__ h,
          __nv_bfloat16* __restrict__ l, int n)
{
    int i = (blockIdx.x * 256 + threadIdx.x) * 4;
    if (i >= n) return;
    float4 v = *(const float4*)(x + i);
    __nv_bfloat16 h0 = __float2bfloat16(v.x), h1 = __float2bfloat16(v.y);
    __nv_bfloat16 h2 = __float2bfloat16(v.z), h3 = __float2bfloat16(v.w);
    __nv_bfloat16 l0 = __float2bfloat16(v.x - __bfloat162float(h0));
    __nv_bfloat16 l1 = __float2bfloat16(v.y - __bfloat162float(h1));
    __nv_bfloat16 l2 = __float2bfloat16(v.z - __bfloat162float(h2));
    __nv_bfloat16 l3 = __float2bfloat16(v.w - __bfloat162float(h3));
    ((__nv_bfloat162*)(h + i))[0] = __halves2bfloat162(h0, h1);
    ((__nv_bfloat162*)(h + i))[1] = __halves2bfloat162(h2, h3);
    ((__nv_bfloat162*)(l + i))[0] = __halves2bfloat162(l0, l1);
    ((__nv_bfloat162*)(l + i))[1] = __halves2bfloat162(l2, l3);
}

// ============================ bf16 transpose (64x64 tiles) ===================
// grid MUST be dim3(C/64, R/64)
__global__ void __launch_bounds__(256)
tbf16(const __nv_bfloat16* __restrict__ src, __nv_bfloat16* __restrict__ dst, int R, int C)
{
    __shared__ __nv_bfloat16 t[64][72];
    const int bc = blockIdx.x * 64, br = blockIdx.y * 64;
    const int tid = threadIdx.x;
#pragma unroll
    for (int i = 0; i < 2; ++i) {
        int idx = i * 256 + tid, r = idx >> 3, c8 = (idx & 7) * 8;
        uint4 v = *(const uint4*)(src + (size_t)(br + r) * C + bc + c8);
        *(uint4*)&t[r][c8] = v;
    }
    __syncthreads();
#pragma unroll
    for (int i = 0; i < 2; ++i) {
        int idx = i * 256 + tid, cc = idx >> 3, r8 = (idx & 7) * 8;
        __nv_bfloat16 tmp[8];
#pragma unroll
        for (int j = 0; j < 8; ++j) tmp[j] = t[r8 + j][cc];
        *(uint4*)(dst + (size_t)(bc + cc) * R + br + r8) = *(uint4*)tmp;
    }
}

// ============================ row softmax (512 cols) =========================
__global__ void __launch_bounds__(128)
softmax512(const float* __restrict__ L, __nv_bfloat16* __restrict__ rh,
           __nv_bfloat16* __restrict__ rl, float* __restrict__ rf)
{
    const int row = blockIdx.x;
    const int tid = threadIdx.x;
    const float4 v = ((const float4*)(L + (size_t)row * Kp))[tid];

    float m = fmaxf(fmaxf(v.x, v.y), fmaxf(v.z, v.w));
#pragma unroll
    for (int o = 16; o; o >>= 1) m = fmaxf(m, __shfl_xor_sync(0xffffffffu, m, o));
    __shared__ float sred[4];
    if ((tid & 31) == 0) sred[tid >> 5] = m;
    __syncthreads();
    m = fmaxf(fmaxf(sred[0], sred[1]), fmaxf(sred[2], sred[3]));

    float4 e;
    e.x = expf(v.x - m); e.y = expf(v.y - m);
    e.z = expf(v.z - m); e.w = expf(v.w - m);
    float s = (e.x + e.y) + (e.z + e.w);
#pragma unroll
    for (int o = 16; o; o >>= 1) s += __shfl_xor_sync(0xffffffffu, s, o);
    __shared__ float ssum[4];
    if ((tid & 31) == 0) ssum[tid >> 5] = s;
    __syncthreads();
    s = (ssum[0] + ssum[1]) + (ssum[2] + ssum[3]);

    float inv = 1.0f / s;
    e.x *= inv; e.y *= inv; e.z *= inv; e.w *= inv;

    __nv_bfloat16 h0 = __float2bfloat16(e.x), h1 = __float2bfloat16(e.y);
    __nv_bfloat16 h2 = __float2bfloat16(e.z), h3 = __float2bfloat16(e.w);
    __nv_bfloat16 l0 = __float2bfloat16(e.x - __bfloat162float(h0));
    __nv_bfloat16 l1 = __float2bfloat16(e.y - __bfloat162float(h1));
    __nv_bfloat16 l2 = __float2bfloat16(e.z - __bfloat162float(h2));
    __nv_bfloat16 l3 = __float2bfloat16(e.w - __bfloat162float(h3));
    __nv_bfloat162* hp = (__nv_bfloat162*)(rh + (size_t)row * Kp);
    __nv_bfloat162* lp = (__nv_bfloat162*)(rl + (size_t)row * Kp);
    hp[tid * 2 + 0] = __halves2bfloat162(h0, h1);
    hp[tid * 2 + 1] = __halves2bfloat162(h2, h3);
    lp[tid * 2 + 0] = __halves2bfloat162(l0, l1);
    lp[tid * 2 + 1] = __halves2bfloat162(l2, l3);
    if (rf) ((float4*)(rf + (size_t)row * Kp))[tid] = e;
}

// ============================ reduce split-K + L2 normalize ==================
__global__ void __launch_bounds__(256)
reduce_norm(const float* __restrict__ parts, __nv_bfloat16* __restrict__ ph,
            __nv_bfloat16* __restrict__ pl)
{
    const int k = blockIdx.x;
    const int tid = threadIdx.x;
    __shared__ float buf[Dd];
    __shared__ float wred[8];
    __shared__ float sden;

    float sq = 0.f;
    for (int d = tid; d < Dd; d += 256) {
        float s = 0.f;
#pragma unroll
        for (int g = 0; g < SEG; ++g)
            s += parts[(size_t)g * Kp * Dd + (size_t)k * Dd + d];
        buf[d] = s;
        sq += s * s;
    }
#pragma unroll
    for (int o = 16; o; o >>= 1) sq += __shfl_xor_sync(0xffffffffu, sq, o);
    if ((tid & 31) == 0) wred[tid >> 5] = sq;
    __syncthreads();
    if (tid == 0) {
        float t = 0.f;
#pragma unroll
        for (int i = 0; i < 8; ++i) t += wred[i];
        sden = sqrtf(t) + 1e-6f;
    }
    __syncthreads();
    const float den = sden;
    for (int d = tid; d < Dd; d += 256) {
        float x = buf[d] / den;
        __nv_bfloat16 h = __float2bfloat16(x);
        ph[(size_t)k * Dd + d] = h;
        pl[(size_t)k * Dd + d] = __float2bfloat16(x - __bfloat162float(h));
    }
}

// ============================ launcher =======================================
extern "C" void kernel_launch(void* const* d_in, const int* in_sizes, int n_in,
                              void* d_out, int out_size)
{
    const float* cls   = (const float*)d_in[0];
    const float* proto = (const float*)d_in[1];
    if (n_in >= 2 && in_sizes[0] < in_sizes[1]) {
        const float* t = cls; cls = proto; proto = t;
    }

    __nv_bfloat16 *cls_h, *cls_l, *clsT_h, *clsT_l, *p_h, *p_l, *pT_h, *pT_l, *r_h, *r_l, *rT_h, *rT_l;
    float *logits, *parts;
    cudaGetSymbolAddress((void**)&cls_h,  g_cls_h);
    cudaGetSymbolAddress((void**)&cls_l,  g_cls_l);
    cudaGetSymbolAddress((void**)&clsT_h, g_clsT_h);
    cudaGetSymbolAddress((void**)&clsT_l, g_clsT_l);
    cudaGetSymbolAddress((void**)&p_h,    g_p_h);
    cudaGetSymbolAddress((void**)&p_l,    g_p_l);
    cudaGetSymbolAddress((void**)&pT_h,   g_pT_h);
    cudaGetSymbolAddress((void**)&pT_l,   g_pT_l);
    cudaGetSymbolAddress((void**)&r_h,    g_r_h);
    cudaGetSymbolAddress((void**)&r_l,    g_r_l);
    cudaGetSymbolAddress((void**)&rT_h,   g_rT_h);
    cudaGetSymbolAddress((void**)&rT_l,   g_rT_l);
    cudaGetSymbolAddress((void**)&logits, g_logits);
    cudaGetSymbolAddress((void**)&parts,  g_parts);

    float* r_out = (float*)d_out;                          // [Bq, Kp]
    float* z_out = (float*)d_out + (size_t)Bq * Kp;        // [Bq, Dd]

    // ---- prep: split cls / proto, transpose cls splits ----
    split_f32<<<(Bq * Dd) / 1024, 256>>>(cls, cls_h, cls_l, Bq * Dd);
    tbf16<<<dim3(Dd / 64, Bq / 64), 256>>>(cls_h, clsT_h, Bq, Dd);
    tbf16<<<dim3(Dd / 64, Bq / 64), 256>>>(cls_l, clsT_l, Bq, Dd);
    split_f32<<<(Kp * Dd) / 1024, 256>>>(proto, p_h, p_l, Kp * Dd);

    dim3 g1(Kp / TN, Bq / TM, 1);        // (4, 64)
    dim3 g2(Dd / TN, Kp / TM, SEG);      // (8, 4, 8)
    dim3 g3(Dd / TN, Bq / TM, 1);        // (8, 64)

    for (int s = 0; s < STAGES; ++s) {
        // logits = cls @ p^T
        mma3x_nt<<<g1, 256>>>(cls_h, cls_l, Dd, p_h, p_l, Dd,
                              Dd, logits, Kp, 0, nullptr);
        softmax512<<<Bq, 128>>>(logits, r_h, r_l, nullptr);
        tbf16<<<dim3(Kp / 64, Bq / 64), 256>>>(r_h, rT_h, Bq, Kp);
        tbf16<<<dim3(Kp / 64, Bq / 64), 256>>>(r_l, rT_l, Bq, Kp);
        // parts[seg] = partial r^T @ cls
        mma3x_nt<<<g2, 256>>>(rT_h, rT_l, Bq, clsT_h, clsT_l, Bq,
                              Bq / SEG, parts, Dd, (size_t)Kp * Dd, nullptr);
        reduce_norm<<<Kp, 256>>>(parts, p_h, p_l);
    }

    // final: logits, softmax (r to d_out), z = r @ p + cls
    mma3x_nt<<<g1, 256>>>(cls_h, cls_l, Dd, p_h, p_l, Dd,
                          Dd, logits, Kp, 0, nullptr);
    softmax512<<<Bq, 128>>>(logits, r_h, r_l, r_out);
    // FIX: tbf16 grid must be (C/64, R/64) = (Dd/64, Kp/64) for p [Kp, Dd]
    tbf16<<<dim3(Dd / 64, Kp / 64), 256>>>(p_h, pT_h, Kp, Dd);
    tbf16<<<dim3(Dd / 64, Kp / 64), 256>>>(p_l, pT_l, Kp, Dd);
    mma3x_nt<<<g3, 256>>>(r_h, r_l, Kp, pT_h, pT_l, Kp,
                          Kp, z_out, Dd, 0, cls);
}

// round 5
// speedup vs baseline: 2.0642x; 1.2672x over previous
#include <cuda_runtime.h>
#include <cuda_bf16.h>
#include <cstdint>
#include <math.h>

#define Bq 8192
#define Dd 1024
#define Kp 512
#define SEG 8
#define STAGES 5

// ============================ device globals (no allocs allowed) ============
__device__ __align__(16) __nv_bfloat16 g_cls_h[(size_t)Bq * Dd];
__device__ __align__(16) __nv_bfloat16 g_cls_l[(size_t)Bq * Dd];
__device__ __align__(16) __nv_bfloat16 g_p_h[(size_t)Kp * Dd];
__device__ __align__(16) __nv_bfloat16 g_p_l[(size_t)Kp * Dd];
__device__ __align__(16) __nv_bfloat16 g_r_h[(size_t)Bq * Kp];
__device__ __align__(16) __nv_bfloat16 g_r_l[(size_t)Bq * Kp];
__device__ __align__(16) float g_logits[(size_t)Bq * Kp];
__device__ __align__(16) float g_parts[(size_t)SEG * Kp * Dd];

// ============================ PTX helpers (base sm_103-safe) =================
__device__ __forceinline__ uint32_t smem_u32(const void* p) {
    uint32_t a;
    asm("{ .reg .u64 t; cvta.to.shared.u64 t, %1; cvt.u32.u64 %0, t; }" : "=r"(a) : "l"(p));
    return a;
}
#define CP_ASYNC16(sa, gp) \
    asm volatile("cp.async.cg.shared.global [%0], [%1], 16;" :: "r"(sa), "l"(gp))
#define CP_COMMIT() asm volatile("cp.async.commit_group;")
#define CP_WAIT1()  asm volatile("cp.async.wait_group 1;")
#define LDSM_X4(r0, r1, r2, r3, addr) \
    asm volatile("ldmatrix.sync.aligned.m8n8.x4.shared.b16 {%0,%1,%2,%3}, [%4];" \
        : "=r"(r0), "=r"(r1), "=r"(r2), "=r"(r3) : "r"(addr))
#define LDSM_X4T(r0, r1, r2, r3, addr) \
    asm volatile("ldmatrix.sync.aligned.m8n8.x4.trans.shared.b16 {%0,%1,%2,%3}, [%4];" \
        : "=r"(r0), "=r"(r1), "=r"(r2), "=r"(r3) : "r"(addr))
#define MMA16816(d, a, b0v, b1v) \
    asm volatile("mma.sync.aligned.m16n8k16.row.col.f32.bf16.bf16.f32 " \
        "{%0,%1,%2,%3}, {%4,%5,%6,%7}, {%8,%9}, {%0,%1,%2,%3};" \
        : "+f"((d)[0]), "+f"((d)[1]), "+f"((d)[2]), "+f"((d)[3]) \
        : "r"((a)[0]), "r"((a)[1]), "r"((a)[2]), "r"((a)[3]), "r"(b0v), "r"(b1v))

// Tiles: CTA 128x128, 8 warps (2x4), warp 64x32, 4x4 of m16n8, KC=32, 3 stages.
#define KC 32
#define SROW 40      // NT-tile row stride in bf16 (80 B)  — m/n-major tiles
#define TROW 136     // trans-tile row stride in bf16 (272 B) — b/k-major tiles
#define NT_STG (128 * SROW * 2)        // 10240 B per stage per operand
#define TT_STG (KC * TROW * 2)         // 8704 B per stage per operand
#define SMEM_NT (6 * NT_STG)           // 61440
#define SMEM_TT (6 * TT_STG)           // 52224
#define SMEM_NN (3 * NT_STG + 3 * TT_STG)  // 56832

// ---------------- shared epilogue ----------------
__device__ __forceinline__ void epilogue(float acc[4][4][4], float* C, int ldc,
                                         int bm, int bn, int wm, int wn, int lane,
                                         const float* addsrc)
{
#pragma unroll
    for (int mt = 0; mt < 4; ++mt) {
        const int r0 = bm + wm * 64 + mt * 16 + (lane >> 2);
#pragma unroll
        for (int nt = 0; nt < 4; ++nt) {
            const int col = bn + wn * 32 + nt * 8 + (lane & 3) * 2;
            float2 v0 = make_float2(acc[mt][nt][0], acc[mt][nt][1]);
            float2 v1 = make_float2(acc[mt][nt][2], acc[mt][nt][3]);
            if (addsrc) {
                const float2 a0 = *(const float2*)(addsrc + (size_t)r0 * ldc + col);
                const float2 a1 = *(const float2*)(addsrc + (size_t)(r0 + 8) * ldc + col);
                v0.x += a0.x; v0.y += a0.y;
                v1.x += a1.x; v1.y += a1.y;
            }
            *(float2*)(C + (size_t)r0 * ldc + col) = v0;
            *(float2*)(C + (size_t)(r0 + 8) * ldc + col) = v1;
        }
    }
}

// ============================ GEMM NT: logits = cls @ p^T ====================
// A[m][K] row-major (K-major), B[n][K] row-major. 3x split as K-concatenation.
__global__ void __launch_bounds__(256, 2)
gemm_nt(const __nv_bfloat16* __restrict__ Ah, const __nv_bfloat16* __restrict__ Al, int lda,
        const __nv_bfloat16* __restrict__ Bh, const __nv_bfloat16* __restrict__ Bl, int ldb,
        int Ksrc, float* __restrict__ C, int ldc)
{
    extern __shared__ char smem[];
    const uint32_t sAb = smem_u32(smem);
    const uint32_t sBb = sAb + 3 * NT_STG;
    const int tid = threadIdx.x, lane = tid & 31, wid = tid >> 5;
    const int wm = wid >> 2, wn = wid & 3;
    const int bm = blockIdx.y * 128, bn = blockIdx.x * 128;

    float acc[4][4][4] = {};
    const int cpb = Ksrc / KC, nch = 3 * cpb;
    const int lrow = tid >> 2, lcb = (tid & 3) * 16;

    auto issue = [&](int c) {
        const int stg = c % 3;
        const int t = c / cpb;
        const size_t kk = (size_t)(c - t * cpb) * KC;
        const __nv_bfloat16* As = (t == 1) ? Al : Ah;
        const __nv_bfloat16* Bs = (t == 2) ? Bl : Bh;
        const uint32_t sa = sAb + stg * NT_STG, sb = sBb + stg * NT_STG;
#pragma unroll
        for (int it = 0; it < 2; ++it) {
            int row = lrow + it * 64;
            CP_ASYNC16(sa + row * 80 + lcb, As + (size_t)(bm + row) * lda + kk + lcb / 2);
            CP_ASYNC16(sb + row * 80 + lcb, Bs + (size_t)(bn + row) * ldb + kk + lcb / 2);
        }
        CP_COMMIT();
    };

    issue(0); issue(1);
    for (int c = 0; c < nch; ++c) {
        CP_WAIT1();
        __syncthreads();
        const int buf = c % 3;
        const uint32_t sa = sAb + buf * NT_STG, sb = sBb + buf * NT_STG;
#pragma unroll
        for (int kg = 0; kg < 2; ++kg) {
            const int kb = kg * 32;
            uint32_t a[4][4], bf[2][4];
#pragma unroll
            for (int mt = 0; mt < 4; ++mt) {
                uint32_t ad = sa + (uint32_t)(wm * 64 + mt * 16 + (lane & 15)) * 80
                            + kb + ((lane >> 4) << 4);
                LDSM_X4(a[mt][0], a[mt][1], a[mt][2], a[mt][3], ad);
            }
#pragma unroll
            for (int nh = 0; nh < 2; ++nh) {
                uint32_t bd = sb + (uint32_t)(wn * 32 + nh * 16 + ((lane >> 3) & 1) * 8 + (lane & 7)) * 80
                            + kb + ((lane >> 4) << 4);
                LDSM_X4(bf[nh][0], bf[nh][1], bf[nh][2], bf[nh][3], bd);
            }
#pragma unroll
            for (int nt = 0; nt < 4; ++nt) {
                const int nh = nt >> 1, lo = nt & 1;
                const uint32_t b0 = bf[nh][lo], b1 = bf[nh][lo + 2];
#pragma unroll
                for (int mt = 0; mt < 4; ++mt)
                    MMA16816(acc[mt][nt], a[mt], b0, b1);
            }
        }
        if (c + 2 < nch) issue(c + 2);
    }
    epilogue(acc, C, ldc, bm, bn, wm, wn, lane, nullptr);
}

// ============================ GEMM TT: parts[seg] = r^T @ cls ================
// A = r[b][m] (trans tiles), B = cls[b][n] (trans tiles), reduction over b.
__global__ void __launch_bounds__(256, 2)
gemm_tt(const __nv_bfloat16* __restrict__ Ah, const __nv_bfloat16* __restrict__ Al, int lda,
        const __nv_bfloat16* __restrict__ Bh, const __nv_bfloat16* __restrict__ Bl, int ldb,
        int Kslab, float* __restrict__ C, int ldc, size_t zstride)
{
    extern __shared__ char smem[];
    const uint32_t sRb = smem_u32(smem);
    const uint32_t sCb = sRb + 3 * TT_STG;
    const int tid = threadIdx.x, lane = tid & 31, wid = tid >> 5;
    const int wm = wid >> 2, wn = wid & 3;
    const int bm = blockIdx.y * 128, bn = blockIdx.x * 128;
    const int b0seg = blockIdx.z * Kslab;
    C += (size_t)blockIdx.z * zstride;

    float acc[4][4][4] = {};
    const int cpb = Kslab / KC, nch = 3 * cpb;
    const int lrow = tid >> 3, lc16 = (tid & 7) * 16;   // row 0..31, col in elems

    auto issue = [&](int c) {
        const int stg = c % 3;
        const int t = c / cpb;
        const int kk = (c - t * cpb) * KC;
        const __nv_bfloat16* As = (t == 1) ? Al : Ah;
        const __nv_bfloat16* Bs = (t == 2) ? Bl : Bh;
        const uint32_t sr = sRb + stg * TT_STG, sc = sCb + stg * TT_STG;
        const size_t gb = (size_t)(b0seg + kk + lrow);
        CP_ASYNC16(sr + lrow * 272 + lc16 * 2,      As + gb * lda + bm + lc16);
        CP_ASYNC16(sr + lrow * 272 + lc16 * 2 + 16, As + gb * lda + bm + lc16 + 8);
        CP_ASYNC16(sc + lrow * 272 + lc16 * 2,      Bs + gb * ldb + bn + lc16);
        CP_ASYNC16(sc + lrow * 272 + lc16 * 2 + 16, Bs + gb * ldb + bn + lc16 + 8);
        CP_COMMIT();
    };

    issue(0); issue(1);
    for (int c = 0; c < nch; ++c) {
        CP_WAIT1();
        __syncthreads();
        const int buf = c % 3;
        const uint32_t sr = sRb + buf * TT_STG, sc = sCb + buf * TT_STG;
#pragma unroll
        for (int kg = 0; kg < 2; ++kg) {
            uint32_t a[4][4], bf[2][4];
#pragma unroll
            for (int mt = 0; mt < 4; ++mt) {
                uint32_t ad = sr + (uint32_t)(kg * 16 + ((lane >> 4) << 3) + (lane & 7)) * 272
                            + (uint32_t)(wm * 64 + mt * 16 + ((lane >> 3) & 1) * 8) * 2;
                LDSM_X4T(a[mt][0], a[mt][1], a[mt][2], a[mt][3], ad);
            }
#pragma unroll
            for (int nh = 0; nh < 2; ++nh) {
                uint32_t bd = sc + (uint32_t)(kg * 16 + ((lane >> 3) & 1) * 8 + (lane & 7)) * 272
                            + (uint32_t)(wn * 32 + nh * 16 + ((lane >> 4) << 3)) * 2;
                LDSM_X4T(bf[nh][0], bf[nh][1], bf[nh][2], bf[nh][3], bd);
            }
#pragma unroll
            for (int nt = 0; nt < 4; ++nt) {
                const int nh = nt >> 1, w = nt & 1;
                const uint32_t b0 = bf[nh][w * 2], b1 = bf[nh][w * 2 + 1];
#pragma unroll
                for (int mt = 0; mt < 4; ++mt)
                    MMA16816(acc[mt][nt], a[mt], b0, b1);
            }
        }
        if (c + 2 < nch) issue(c + 2);
    }
    epilogue(acc, C, ldc, bm, bn, wm, wn, lane, nullptr);
}

// ============================ GEMM NN: z = r @ p + cls =======================
// A = r[m=b][k] row-major (NT-style tiles), B = p[k][n] (trans tiles).
__global__ void __launch_bounds__(256, 2)
gemm_nn(const __nv_bfloat16* __restrict__ Ah, const __nv_bfloat16* __restrict__ Al, int lda,
        const __nv_bfloat16* __restrict__ Bh, const __nv_bfloat16* __restrict__ Bl, int ldb,
        int Ksrc, float* __restrict__ C, int ldc, const float* __restrict__ addsrc)
{
    extern __shared__ char smem[];
    const uint32_t sAb = smem_u32(smem);
    const uint32_t sBb = sAb + 3 * NT_STG;
    const int tid = threadIdx.x, lane = tid & 31, wid = tid >> 5;
    const int wm = wid >> 2, wn = wid & 3;
    const int bm = blockIdx.y * 128, bn = blockIdx.x * 128;

    float acc[4][4][4] = {};
    const int cpb = Ksrc / KC, nch = 3 * cpb;
    const int lrow = tid >> 2, lcb = (tid & 3) * 16;    // A loader
    const int trow = tid >> 3, tc16 = (tid & 7) * 16;   // B loader

    auto issue = [&](int c) {
        const int stg = c % 3;
        const int t = c / cpb;
        const int kk = (c - t * cpb) * KC;
        const __nv_bfloat16* As = (t == 1) ? Al : Ah;
        const __nv_bfloat16* Bs = (t == 2) ? Bl : Bh;
        const uint32_t sa = sAb + stg * NT_STG, sb = sBb + stg * TT_STG;
#pragma unroll
        for (int it = 0; it < 2; ++it) {
            int row = lrow + it * 64;
            CP_ASYNC16(sa + row * 80 + lcb, As + (size_t)(bm + row) * lda + kk + lcb / 2);
        }
        CP_ASYNC16(sb + trow * 272 + tc16 * 2,      Bs + (size_t)(kk + trow) * ldb + bn + tc16);
        CP_ASYNC16(sb + trow * 272 + tc16 * 2 + 16, Bs + (size_t)(kk + trow) * ldb + bn + tc16 + 8);
        CP_COMMIT();
    };

    issue(0); issue(1);
    for (int c = 0; c < nch; ++c) {
        CP_WAIT1();
        __syncthreads();
        const int buf = c % 3;
        const uint32_t sa = sAb + buf * NT_STG, sb = sBb + buf * TT_STG;
#pragma unroll
        for (int kg = 0; kg < 2; ++kg) {
            const int kb = kg * 32;
            uint32_t a[4][4], bf[2][4];
#pragma unroll
            for (int mt = 0; mt < 4; ++mt) {
                uint32_t ad = sa + (uint32_t)(wm * 64 + mt * 16 + (lane & 15)) * 80
                            + kb + ((lane >> 4) << 4);
                LDSM_X4(a[mt][0], a[mt][1], a[mt][2], a[mt][3], ad);
            }
#pragma unroll
            for (int nh = 0; nh < 2; ++nh) {
                uint32_t bd = sb + (uint32_t)(kg * 16 + ((lane >> 3) & 1) * 8 + (lane & 7)) * 272
                            + (uint32_t)(wn * 32 + nh * 16 + ((lane >> 4) << 3)) * 2;
                LDSM_X4T(bf[nh][0], bf[nh][1], bf[nh][2], bf[nh][3], bd);
            }
#pragma unroll
            for (int nt = 0; nt < 4; ++nt) {
                const int nh = nt >> 1, w = nt & 1;
                const uint32_t b0 = bf[nh][w * 2], b1 = bf[nh][w * 2 + 1];
#pragma unroll
                for (int mt = 0; mt < 4; ++mt)
                    MMA16816(acc[mt][nt], a[mt], b0, b1);
            }
        }
        if (c + 2 < nch) issue(c + 2);
    }
    epilogue(acc, C, ldc, bm, bn, wm, wn, lane, addsrc);
}

// ============================ split fp32 -> bf16 hi/lo =======================
__global__ void __launch_bounds__(256)
split_f32(const float* __restrict__ x, __nv_bfloat16* __restrict__ h,
          __nv_bfloat16* __restrict__ l, int n)
{
    int i = (blockIdx.x * 256 + threadIdx.x) * 4;
    if (i >= n) return;
    float4 v = *(const float4*)(x + i);
    __nv_bfloat16 h0 = __float2bfloat16(v.x), h1 = __float2bfloat16(v.y);
    __nv_bfloat16 h2 = __float2bfloat16(v.z), h3 = __float2bfloat16(v.w);
    __nv_bfloat16 l0 = __float2bfloat16(v.x - __bfloat162float(h0));
    __nv_bfloat16 l1 = __float2bfloat16(v.y - __bfloat162float(h1));
    __nv_bfloat16 l2 = __float2bfloat16(v.z - __bfloat162float(h2));
    __nv_bfloat16 l3 = __float2bfloat16(v.w - __bfloat162float(h3));
    ((__nv_bfloat162*)(h + i))[0] = __halves2bfloat162(h0, h1);
    ((__nv_bfloat162*)(h + i))[1] = __halves2bfloat162(h2, h3);
    ((__nv_bfloat162*)(l + i))[0] = __halves2bfloat162(l0, l1);
    ((__nv_bfloat162*)(l + i))[1] = __halves2bfloat162(l2, l3);
}

// ============================ row softmax (512 cols) =========================
__global__ void __launch_bounds__(128)
softmax512(const float* __restrict__ L, __nv_bfloat16* __restrict__ rh,
           __nv_bfloat16* __restrict__ rl, float* __restrict__ rf)
{
    const int row = blockIdx.x;
    const int tid = threadIdx.x;
    const float4 v = ((const float4*)(L + (size_t)row * Kp))[tid];

    float m = fmaxf(fmaxf(v.x, v.y), fmaxf(v.z, v.w));
#pragma unroll
    for (int o = 16; o; o >>= 1) m = fmaxf(m, __shfl_xor_sync(0xffffffffu, m, o));
    __shared__ float sred[4];
    if ((tid & 31) == 0) sred[tid >> 5] = m;
    __syncthreads();
    m = fmaxf(fmaxf(sred[0], sred[1]), fmaxf(sred[2], sred[3]));

    float4 e;
    e.x = expf(v.x - m); e.y = expf(v.y - m);
    e.z = expf(v.z - m); e.w = expf(v.w - m);
    float s = (e.x + e.y) + (e.z + e.w);
#pragma unroll
    for (int o = 16; o; o >>= 1) s += __shfl_xor_sync(0xffffffffu, s, o);
    __shared__ float ssum[4];
    if ((tid & 31) == 0) ssum[tid >> 5] = s;
    __syncthreads();
    s = (ssum[0] + ssum[1]) + (ssum[2] + ssum[3]);

    float inv = 1.0f / s;
    e.x *= inv; e.y *= inv; e.z *= inv; e.w *= inv;

    __nv_bfloat16 h0 = __float2bfloat16(e.x), h1 = __float2bfloat16(e.y);
    __nv_bfloat16 h2 = __float2bfloat16(e.z), h3 = __float2bfloat16(e.w);
    __nv_bfloat16 l0 = __float2bfloat16(e.x - __bfloat162float(h0));
    __nv_bfloat16 l1 = __float2bfloat16(e.y - __bfloat162float(h1));
    __nv_bfloat16 l2 = __float2bfloat16(e.z - __bfloat162float(h2));
    __nv_bfloat16 l3 = __float2bfloat16(e.w - __bfloat162float(h3));
    __nv_bfloat162* hp = (__nv_bfloat162*)(rh + (size_t)row * Kp);
    __nv_bfloat162* lp = (__nv_bfloat162*)(rl + (size_t)row * Kp);
    hp[tid * 2 + 0] = __halves2bfloat162(h0, h1);
    hp[tid * 2 + 1] = __halves2bfloat162(h2, h3);
    lp[tid * 2 + 0] = __halves2bfloat162(l0, l1);
    lp[tid * 2 + 1] = __halves2bfloat162(l2, l3);
    if (rf) ((float4*)(rf + (size_t)row * Kp))[tid] = e;
}

// ============================ reduce split-K + L2 normalize ==================
__global__ void __launch_bounds__(256)
reduce_norm(const float* __restrict__ parts, __nv_bfloat16* __restrict__ ph,
            __nv_bfloat16* __restrict__ pl)
{
    const int k = blockIdx.x;
    const int tid = threadIdx.x;
    __shared__ float buf[Dd];
    __shared__ float wred[8];
    __shared__ float sden;

    float sq = 0.f;
    for (int d = tid; d < Dd; d += 256) {
        float s = 0.f;
#pragma unroll
        for (int g = 0; g < SEG; ++g)
            s += parts[(size_t)g * Kp * Dd + (size_t)k * Dd + d];
        buf[d] = s;
        sq += s * s;
    }
#pragma unroll
    for (int o = 16; o; o >>= 1) sq += __shfl_xor_sync(0xffffffffu, sq, o);
    if ((tid & 31) == 0) wred[tid >> 5] = sq;
    __syncthreads();
    if (tid == 0) {
        float t = 0.f;
#pragma unroll
        for (int i = 0; i < 8; ++i) t += wred[i];
        sden = sqrtf(t) + 1e-6f;
    }
    __syncthreads();
    const float den = sden;
    for (int d = tid; d < Dd; d += 256) {
        float x = buf[d] / den;
        __nv_bfloat16 h = __float2bfloat16(x);
        ph[(size_t)k * Dd + d] = h;
        pl[(size_t)k * Dd + d] = __float2bfloat16(x - __bfloat162float(h));
    }
}

// ============================ launcher =======================================
extern "C" void kernel_launch(void* const* d_in, const int* in_sizes, int n_in,
                              void* d_out, int out_size)
{
    const float* cls   = (const float*)d_in[0];
    const float* proto = (const float*)d_in[1];
    if (n_in >= 2 && in_sizes[0] < in_sizes[1]) {
        const float* t = cls; cls = proto; proto = t;
    }

    __nv_bfloat16 *cls_h, *cls_l, *p_h, *p_l, *r_h, *r_l;
    float *logits, *parts;
    cudaGetSymbolAddress((void**)&cls_h,  g_cls_h);
    cudaGetSymbolAddress((void**)&cls_l,  g_cls_l);
    cudaGetSymbolAddress((void**)&p_h,    g_p_h);
    cudaGetSymbolAddress((void**)&p_l,    g_p_l);
    cudaGetSymbolAddress((void**)&r_h,    g_r_h);
    cudaGetSymbolAddress((void**)&r_l,    g_r_l);
    cudaGetSymbolAddress((void**)&logits, g_logits);
    cudaGetSymbolAddress((void**)&parts,  g_parts);

    cudaFuncSetAttribute(gemm_nt, cudaFuncAttributeMaxDynamicSharedMemorySize, SMEM_NT);
    cudaFuncSetAttribute(gemm_tt, cudaFuncAttributeMaxDynamicSharedMemorySize, SMEM_TT);
    cudaFuncSetAttribute(gemm_nn, cudaFuncAttributeMaxDynamicSharedMemorySize, SMEM_NN);

    float* r_out = (float*)d_out;                          // [Bq, Kp]
    float* z_out = (float*)d_out + (size_t)Bq * Kp;        // [Bq, Dd]

    // ---- prep: split cls / proto into bf16 hi/lo (no transposes needed) ----
    split_f32<<<(Bq * Dd) / 1024, 256>>>(cls, cls_h, cls_l, Bq * Dd);
    split_f32<<<(Kp * Dd) / 1024, 256>>>(proto, p_h, p_l, Kp * Dd);

    dim3 g1(Kp / 128, Bq / 128);         // (4, 64)
    dim3 g2(Dd / 128, Kp / 128, SEG);    // (8, 4, 8)
    dim3 g3(Dd / 128, Bq / 128);         // (8, 64)

    for (int s = 0; s < STAGES; ++s) {
        gemm_nt<<<g1, 256, SMEM_NT>>>(cls_h, cls_l, Dd, p_h, p_l, Dd,
                                      Dd, logits, Kp);
        softmax512<<<Bq, 128>>>(logits, r_h, r_l, nullptr);
        gemm_tt<<<g2, 256, SMEM_TT>>>(r_h, r_l, Kp, cls_h, cls_l, Dd,
                                      Bq / SEG, parts, Dd, (size_t)Kp * Dd);
        reduce_norm<<<Kp, 256>>>(parts, p_h, p_l);
    }

    // final: logits, softmax (r into d_out), z = r @ p + cls
    gemm_nt<<<g1, 256, SMEM_NT>>>(cls_h, cls_l, Dd, p_h, p_l, Dd,
                                  Dd, logits, Kp);
    softmax512<<<Bq, 128>>>(logits, r_h, r_l, r_out);
    gemm_nn<<<g3, 256, SMEM_NN>>>(r_h, r_l, Kp, p_h, p_l, Dd,
                                  Kp, z_out, Dd, cls);
}